// round 15
// baseline (speedup 1.0000x reference)
#include <cuda_runtime.h>
#include <cuda_fp16.h>
#include <math.h>
#include <stdint.h>

// Problem constants
#define BATCH 2
#define NB    9216          // H*W per batch (96*96)
#define NPIX  (BATCH * NB)  // 18432
#define CIN   384
#define C1    256
#define C2    128
#define MASK_THR 0.2f
#define NT64  144           // 64-row j-tiles per batch
#define NT128 72            // 128-row i-tiles per batch

// Scratch (device globals: no allocations allowed)
__device__ __align__(256) __half g_xth[(size_t)NPIX * CIN]; // X^T hi [bp][c]
__device__ __align__(256) __half g_xtl[(size_t)NPIX * CIN]; // X^T lo
__device__ __align__(256) __half g_w1h[(size_t)C1 * CIN];
__device__ __align__(256) __half g_w1l[(size_t)C1 * CIN];
__device__ __align__(256) __half g_w2h[(size_t)C2 * C1];
__device__ __align__(256) __half g_w2l[(size_t)C2 * C1];
__device__ __align__(256) __half g_h1h[(size_t)NPIX * C1];  // relu(h1) hi
__device__ __align__(256) __half g_h1l[(size_t)NPIX * C1];  // relu(h1) lo
__device__ float  g_feat[(size_t)NPIX * C2];   // [n][c]
__device__ float  g_rf[(size_t)NPIX * C2];     // [n][c] normalized fp32
__device__ __align__(256) __half g_hih[(size_t)NPIX * C2]; // rf fp16 hi
__device__ __align__(256) __half g_loh[(size_t)NPIX * C2]; // rf fp16 residual
// row-fold top-1 candidates: [s-slot 0..3][row]
__device__ float  g_rv[(size_t)4 * NPIX];
__device__ int    g_ri[(size_t)4 * NPIX];
// column-fold top-1 candidates: [batch][tj64][ti][64 rows]
__device__ float  g_cv[(size_t)BATCH * NT64 * NT128 * 64];
__device__ int    g_ci[(size_t)BATCH * NT64 * NT128 * 64];
__device__ int    g_nn[NPIX];

// ---------------------------------------------------------------------------
// PTX helpers (baseline ISA only — compute_103 safe)
// ---------------------------------------------------------------------------
__device__ __forceinline__ uint32_t smem_u32(const void* p) {
    return (uint32_t)__cvta_generic_to_shared(p);
}
#define CP16(dst, src) \
    asm volatile("cp.async.cg.shared.global [%0], [%1], 16;" :: "r"(dst), "l"(src))
#define CPCOMMIT() asm volatile("cp.async.commit_group;")
#define CPWAIT0()  asm volatile("cp.async.wait_group 0;" ::: "memory")

#define LDSM4(r0, r1, r2, r3, addr) \
    asm volatile("ldmatrix.sync.aligned.m8n8.x4.shared.b16 {%0,%1,%2,%3}, [%4];" \
        : "=r"(r0), "=r"(r1), "=r"(r2), "=r"(r3) : "r"(addr))

#define MMA16816(c, a, b) \
    asm volatile("mma.sync.aligned.m16n8k16.row.col.f32.f16.f16.f32 " \
        "{%0,%1,%2,%3}, {%4,%5,%6,%7}, {%8,%9}, {%0,%1,%2,%3};" \
        : "+f"((c)[0]), "+f"((c)[1]), "+f"((c)[2]), "+f"((c)[3]) \
        : "r"((a)[0]), "r"((a)[1]), "r"((a)[2]), "r"((a)[3]), \
          "r"((b)[0]), "r"((b)[1]))

// swizzle for 256B rows (sim kernel), 16B chunk c in 0..15
__device__ __forceinline__ uint32_t sw_off(int r, int c) {
    return (uint32_t)(r * 256 + ((c ^ (r & 7)) << 4));
}
// swizzle for 128B rows (MLP gemms), 16B chunk c in 0..7
__device__ __forceinline__ uint32_t sw128(int r, int c) {
    return (uint32_t)(r * 128 + ((c ^ (r & 7)) << 4));
}

// Top-1 insert with jax top_k tie-breaking (equal value -> lower index).
__device__ __forceinline__ void ins1(float v, int j, float& v1, int& i1) {
    if (v > v1 || (v == v1 && j < i1)) { v1 = v; i1 = j; }
}

// ---------------------------------------------------------------------------
// Prep: split W1/W2 into fp16 hi/lo
// ---------------------------------------------------------------------------
__global__ void splitw_kernel(const float* __restrict__ W1,
                              const float* __restrict__ W2) {
    int i = blockIdx.x * 256 + threadIdx.x;
    if (i < C1 * CIN) {
        float v = W1[i];
        __half h = __float2half_rn(v);
        g_w1h[i] = h;
        g_w1l[i] = __float2half_rn(v - __half2float(h));
    } else {
        int j = i - C1 * CIN;
        if (j < C2 * C1) {
            float v = W2[j];
            __half h = __float2half_rn(v);
            g_w2h[j] = h;
            g_w2l[j] = __float2half_rn(v - __half2float(h));
        }
    }
}

// ---------------------------------------------------------------------------
// Prep: transpose X [b][c][hw] -> Xt [b][hw][c], split fp16 hi/lo
// ---------------------------------------------------------------------------
__global__ void transpose_split_kernel(const float* __restrict__ X) {
    __shared__ float s[32][33];
    const int b = blockIdx.z;
    const int hw0 = blockIdx.x * 32;
    const int c0 = blockIdx.y * 32;
    const int tx = threadIdx.x, ty = threadIdx.y;
    const float* Xb = X + ((size_t)b * CIN + c0) * NB + hw0;
#pragma unroll
    for (int i = 0; i < 4; i++) {
        int cl = ty + 8 * i;
        s[cl][tx] = Xb[(size_t)cl * NB + tx];
    }
    __syncthreads();
#pragma unroll
    for (int i = 0; i < 4; i++) {
        int hwl = ty + 8 * i;
        float v = s[tx][hwl];
        __half h = __float2half_rn(v);
        size_t o = ((size_t)b * NB + hw0 + hwl) * CIN + c0 + tx;
        g_xth[o] = h;
        g_xtl[o] = __float2half_rn(v - __half2float(h));
    }
}

// ---------------------------------------------------------------------------
// Tensor-core MLP GEMM machinery (round-12, unchanged)
// ---------------------------------------------------------------------------
#define MLP_SMEM 98304

__device__ __forceinline__ void mlp_stage(uint32_t sb, int buf,
                                          const __half* __restrict__ Ah,
                                          const __half* __restrict__ Al,
                                          const __half* __restrict__ Bh,
                                          const __half* __restrict__ Bl,
                                          int m0, int n0, int kc0, int K, int t) {
    const uint32_t sA = sb + (uint32_t)buf * 32768u;
    const uint32_t sB = sb + 65536u + (uint32_t)buf * 16384u;
#pragma unroll
    for (int e = 0; e < 4; e++) {
        int id = e * 256 + t;
        int r = id >> 3, c = id & 7;
        uint32_t o = sw128(r, c);
        const size_t off = (size_t)(m0 + r) * K + kc0 + c * 8;
        CP16(sA + o,          Ah + off);
        CP16(sA + 16384u + o, Al + off);
    }
#pragma unroll
    for (int e = 0; e < 2; e++) {
        int id = e * 256 + t;
        int r = id >> 3, c = id & 7;
        uint32_t o = sw128(r, c);
        const size_t off = (size_t)(n0 + r) * K + kc0 + c * 8;
        CP16(sB + o,         Bh + off);
        CP16(sB + 8192u + o, Bl + off);
    }
}

#define MLP_COMPUTE_CHUNK(aB, bB)                                              \
    _Pragma("unroll")                                                          \
    for (int ks = 0; ks < 4; ks++) {                                           \
        const int ck = ks * 2;                                                 \
        uint32_t ah[4], al[4];                                                 \
        LDSM4(ah[0], ah[1], ah[2], ah[3], (aB) + sw128(ar, ck + cb));          \
        LDSM4(al[0], al[1], al[2], al[3], (aB) + 16384u + sw128(ar, ck + cb)); \
        uint32_t bf[16];                                                       \
        _Pragma("unroll")                                                      \
        for (int nb = 0; nb < 4; nb++) {                                       \
            uint32_t ad = (bB) + sw128(nb * 16 + brn, ck + bcb);               \
            LDSM4(bf[4*nb], bf[4*nb+1], bf[4*nb+2], bf[4*nb+3], ad);           \
        }                                                                      \
        _Pragma("unroll")                                                      \
        for (int nf = 0; nf < 8; nf++) MMA16816(acc[nf], ah, bf + 2 * nf);     \
        _Pragma("unroll")                                                      \
        for (int nf = 0; nf < 8; nf++) MMA16816(acc[nf], al, bf + 2 * nf);     \
        _Pragma("unroll")                                                      \
        for (int nb = 0; nb < 4; nb++) {                                       \
            uint32_t ad = (bB) + 8192u + sw128(nb * 16 + brn, ck + bcb);       \
            LDSM4(bf[4*nb], bf[4*nb+1], bf[4*nb+2], bf[4*nb+3], ad);           \
        }                                                                      \
        _Pragma("unroll")                                                      \
        for (int nf = 0; nf < 8; nf++) MMA16816(acc[nf], ah, bf + 2 * nf);     \
    }

__global__ void __launch_bounds__(256, 2) gemm1_mma_kernel(const float* __restrict__ b1v) {
    extern __shared__ __align__(1024) char sm[];
    const int t = threadIdx.x, w = t >> 5, l = t & 31;
    const int m0 = blockIdx.x * 128, n0 = blockIdx.y * 64;
    const uint32_t sb = smem_u32(sm);
    const int sub = l >> 3;
    const int ar  = w * 16 + ((sub & 1) << 3) + (l & 7);
    const int cb  = sub >> 1;
    const int brn = ((sub >> 1) << 3) + (l & 7);
    const int bcb = sub & 1;

    mlp_stage(sb, 0, g_xth, g_xtl, g_w1h, g_w1l, m0, n0, 0, CIN, t);
    CPCOMMIT();

    float acc[8][4];
#pragma unroll
    for (int nf = 0; nf < 8; nf++)
#pragma unroll
        for (int q = 0; q < 4; q++) acc[nf][q] = 0.f;

    const int NCH = CIN / 64;
    for (int kc = 0; kc < NCH; kc++) {
        CPWAIT0();
        __syncthreads();
        if (kc + 1 < NCH) {
            mlp_stage(sb, (kc + 1) & 1, g_xth, g_xtl, g_w1h, g_w1l,
                      m0, n0, (kc + 1) * 64, CIN, t);
            CPCOMMIT();
        }
        const uint32_t aB = sb + (uint32_t)(kc & 1) * 32768u;
        const uint32_t bB = sb + 65536u + (uint32_t)(kc & 1) * 16384u;
        MLP_COMPUTE_CHUNK(aB, bB)
        __syncthreads();
    }

    const int rowa = m0 + w * 16 + (l >> 2);
#pragma unroll
    for (int nf = 0; nf < 8; nf++) {
        int col = n0 + nf * 8 + (l & 3) * 2;
        float b0 = b1v[col], b1 = b1v[col + 1];
        float v0 = fmaxf(acc[nf][0] + b0, 0.f);
        float v1 = fmaxf(acc[nf][1] + b1, 0.f);
        float v2 = fmaxf(acc[nf][2] + b0, 0.f);
        float v3 = fmaxf(acc[nf][3] + b1, 0.f);
        __half h0 = __float2half_rn(v0), h1 = __float2half_rn(v1);
        __half h2 = __float2half_rn(v2), h3 = __float2half_rn(v3);
        *(__half2*)&g_h1h[(size_t)rowa * C1 + col] = __halves2half2(h0, h1);
        *(__half2*)&g_h1l[(size_t)rowa * C1 + col] = __halves2half2(
            __float2half_rn(v0 - __half2float(h0)),
            __float2half_rn(v1 - __half2float(h1)));
        *(__half2*)&g_h1h[(size_t)(rowa + 8) * C1 + col] = __halves2half2(h2, h3);
        *(__half2*)&g_h1l[(size_t)(rowa + 8) * C1 + col] = __halves2half2(
            __float2half_rn(v2 - __half2float(h2)),
            __float2half_rn(v3 - __half2float(h3)));
    }
}

__global__ void __launch_bounds__(256, 2) gemm2_mma_kernel(const float* __restrict__ b2v) {
    extern __shared__ __align__(1024) char sm[];
    const int t = threadIdx.x, w = t >> 5, l = t & 31;
    const int m0 = blockIdx.x * 128, n0 = blockIdx.y * 64;
    const uint32_t sb = smem_u32(sm);
    const int sub = l >> 3;
    const int ar  = w * 16 + ((sub & 1) << 3) + (l & 7);
    const int cb  = sub >> 1;
    const int brn = ((sub >> 1) << 3) + (l & 7);
    const int bcb = sub & 1;

    mlp_stage(sb, 0, g_h1h, g_h1l, g_w2h, g_w2l, m0, n0, 0, C1, t);
    CPCOMMIT();

    float acc[8][4];
#pragma unroll
    for (int nf = 0; nf < 8; nf++)
#pragma unroll
        for (int q = 0; q < 4; q++) acc[nf][q] = 0.f;

    const int NCH = C1 / 64;
    for (int kc = 0; kc < NCH; kc++) {
        CPWAIT0();
        __syncthreads();
        if (kc + 1 < NCH) {
            mlp_stage(sb, (kc + 1) & 1, g_h1h, g_h1l, g_w2h, g_w2l,
                      m0, n0, (kc + 1) * 64, C1, t);
            CPCOMMIT();
        }
        const uint32_t aB = sb + (uint32_t)(kc & 1) * 32768u;
        const uint32_t bB = sb + 65536u + (uint32_t)(kc & 1) * 16384u;
        MLP_COMPUTE_CHUNK(aB, bB)
        __syncthreads();
    }

    const int rowa = m0 + w * 16 + (l >> 2);
#pragma unroll
    for (int nf = 0; nf < 8; nf++) {
        int col = n0 + nf * 8 + (l & 3) * 2;
        float b0 = b2v[col], b1 = b2v[col + 1];
        float2 ra = make_float2(acc[nf][0] + b0, acc[nf][1] + b1);
        float2 rb = make_float2(acc[nf][2] + b0, acc[nf][3] + b1);
        *(float2*)&g_feat[(size_t)rowa * C2 + col] = ra;
        *(float2*)&g_feat[(size_t)(rowa + 8) * C2 + col] = rb;
    }
}

// ---------------------------------------------------------------------------
// Normalize: rf = feat / max(||feat||, 1e-12); fp32 rf + fp16 hi/lo split.
// ---------------------------------------------------------------------------
__global__ void normalize_kernel() {
    const int n = blockIdx.x;
    const int c = threadIdx.x;
    float v = g_feat[(size_t)n * C2 + c];
    float s = v * v;
#pragma unroll
    for (int off = 16; off; off >>= 1) s += __shfl_xor_sync(0xffffffffu, s, off);
    __shared__ float ws[4];
    if ((c & 31) == 0) ws[c >> 5] = s;
    __syncthreads();
    float tot = ws[0] + ws[1] + ws[2] + ws[3];
    float norm = sqrtf(tot);
    float nf = v / fmaxf(norm, 1e-12f);
    g_rf[(size_t)n * C2 + c] = nf;
    __half hi = __float2half_rn(nf);
    g_hih[(size_t)n * C2 + c] = hi;
    g_loh[(size_t)n * C2 + c] = __float2half_rn(nf - __half2float(hi));
}

// ---------------------------------------------------------------------------
// SYMMETRIC tensor-core similarity, TOP-1-excluding-self version.
// Since sim(i,i)=1 is always row top-1 (unit vectors), the reference's
// top2_idx[:,:,1] == argmax_{j != i} sim(i,j)  (ties -> lower index).
// Each unordered tile pair computed once; folded into row top-1 (i-rows)
// and column top-1 (j-rows).  Diagonal (j==i) masked to -inf in k<2 tiles.
// Partition (validated in R13): row-cover k=tj64-2*ti in [0,nt);
// column-cover only k>=2 (no double count, no self in column side).
// Grid: (36 pair-ids, 4 s, 2 batches) = 288 CTAs -> 2 CTAs/SM.
// ---------------------------------------------------------------------------
#define ALO_BYTES 32768
#define BUFB  32768
#define SIM_SMEM (ALO_BYTES + 2 * BUFB + 4096)   // 100KB

__global__ void __launch_bounds__(256, 2) sim_mma_kernel() {
    extern __shared__ __align__(1024) char sm[];
    const int t = threadIdx.x;
    const int w = t >> 5, l = t & 31;
    const int pid = blockIdx.x;      // 0..35
    const int s   = blockIdx.y;      // 0..3
    const int b   = blockIdx.z;
    const __half* Hsrc = g_hih + (size_t)b * NB * C2;
    const __half* Lsrc = g_loh + (size_t)b * NB * C2;
    const uint32_t sbA = smem_u32(sm);
    const uint32_t bb0 = sbA + ALO_BYTES;
    float* scv = (float*)(sm + ALO_BYTES + 2 * BUFB);
    int*   sci = (int*)(sm + ALO_BYTES + 2 * BUFB + 2048);

    const int sub = l >> 3;
    const int arl = ((sub & 1) << 3) + (l & 7);
    const int cb  = sub >> 1;
    const int ar  = w * 16 + arl;
    const int brn = ((sub >> 1) << 3) + (l & 7);
    const int bcb = sub & 1;

    for (int phase = 0; phase < 2; phase++) {
        const int ti = phase ? (71 - pid) : pid;
        const int i0 = ti * 128;
        const int nt = NT64 - 2 * ti;
        const int count = (nt > s) ? ((nt - s + 3) >> 2) : 0;
        const int ra = i0 + w * 16 + (l >> 2);   // batch-local row A
        const int rb = ra + 8;                    // batch-local row B

        float v1a = -INFINITY, v1b = -INFINITY;
        int   i1a = 0x7fffffff, i1b = 0x7fffffff;

        uint32_t a_hi[8][4];

        if (count > 0) {
            __syncthreads();   // prior phase fully done with B region / colbuf
#pragma unroll
            for (int e = 0; e < 8; e++) {
                int id = e * 256 + t;
                int r = id >> 4, c = id & 15;
                uint32_t o = sw_off(r, c);
                CP16(sbA + o, (const char*)(Lsrc + (size_t)(i0 + r) * C2) + c * 16);
                CP16(bb0 + o, (const char*)(Hsrc + (size_t)(i0 + r) * C2) + c * 16);
            }
            CPCOMMIT(); CPWAIT0();
            __syncthreads();
#pragma unroll
            for (int ks = 0; ks < 8; ks++) {
                uint32_t ad = bb0 + sw_off(ar, ks * 2 + cb);
                LDSM4(a_hi[ks][0], a_hi[ks][1], a_hi[ks][2], a_hi[ks][3], ad);
            }
            __syncthreads();
            {
                const int j0 = (2 * ti + s) * 64;
#pragma unroll
                for (int e = 0; e < 4; e++) {
                    int id = e * 256 + t;
                    int r = id >> 4, c = id & 15;
                    uint32_t o = sw_off(r, c);
                    CP16(bb0 + o,         (const char*)(Hsrc + (size_t)(j0 + r) * C2) + c * 16);
                    CP16(bb0 + 16384 + o, (const char*)(Lsrc + (size_t)(j0 + r) * C2) + c * 16);
                }
                CPCOMMIT();
            }
        }

        for (int m = 0; m < count; m++) {
            const int k = s + 4 * m;
            const int tj64 = 2 * ti + k;
            CPWAIT0();
            __syncthreads();

            if (m + 1 < count) {
                const int j0n = (tj64 + 4) * 64;
                const uint32_t bo = bb0 + (uint32_t)((m + 1) & 1) * BUFB;
#pragma unroll
                for (int e = 0; e < 4; e++) {
                    int id = e * 256 + t;
                    int r = id >> 4, c = id & 15;
                    uint32_t o = bo + sw_off(r, c);
                    CP16(o,         (const char*)(Hsrc + (size_t)(j0n + r) * C2) + c * 16);
                    CP16(o + 16384, (const char*)(Lsrc + (size_t)(j0n + r) * C2) + c * 16);
                }
                CPCOMMIT();
            }

            const uint32_t bo = bb0 + (uint32_t)(m & 1) * BUFB;
            float acc[8][4];
#pragma unroll
            for (int nf = 0; nf < 8; nf++)
#pragma unroll
                for (int q = 0; q < 4; q++) acc[nf][q] = 0.f;

#pragma unroll
            for (int ks = 0; ks < 8; ks++) {
                const int ck = ks * 2;
                uint32_t al[4];
                LDSM4(al[0], al[1], al[2], al[3], sbA + sw_off(ar, ck + cb));
                uint32_t bf[16];
#pragma unroll
                for (int nb = 0; nb < 4; nb++) {
                    uint32_t ad = bo + sw_off(nb * 16 + brn, ck + bcb);
                    LDSM4(bf[4 * nb], bf[4 * nb + 1], bf[4 * nb + 2], bf[4 * nb + 3], ad);
                }
#pragma unroll
                for (int nf = 0; nf < 8; nf++) MMA16816(acc[nf], a_hi[ks], bf + 2 * nf);
#pragma unroll
                for (int nf = 0; nf < 8; nf++) MMA16816(acc[nf], al, bf + 2 * nf);
#pragma unroll
                for (int nb = 0; nb < 4; nb++) {
                    uint32_t ad = bo + 16384 + sw_off(nb * 16 + brn, ck + bcb);
                    LDSM4(bf[4 * nb], bf[4 * nb + 1], bf[4 * nb + 2], bf[4 * nb + 3], ad);
                }
#pragma unroll
                for (int nf = 0; nf < 8; nf++) MMA16816(acc[nf], a_hi[ks], bf + 2 * nf);
            }

            const int cbase = tj64 * 64 + (l & 3) * 2;

            // ---- diagonal mask (only k<2 tiles can contain j==i) ----
            if (k < 2) {
#pragma unroll
                for (int nf = 0; nf < 8; nf++) {
                    int c0 = cbase + nf * 8, c1 = c0 + 1;
                    if (c0 == ra) acc[nf][0] = -INFINITY;
                    if (c1 == ra) acc[nf][1] = -INFINITY;
                    if (c0 == rb) acc[nf][2] = -INFINITY;
                    if (c1 == rb) acc[nf][3] = -INFINITY;
                }
            }

            // ---- row fold, top-1, guarded ----
            float mA = fmaxf(acc[0][0], acc[0][1]);
            float mB = fmaxf(acc[0][2], acc[0][3]);
#pragma unroll
            for (int nf = 1; nf < 8; nf++) {
                mA = fmaxf(mA, fmaxf(acc[nf][0], acc[nf][1]));
                mB = fmaxf(mB, fmaxf(acc[nf][2], acc[nf][3]));
            }
            if (mA >= v1a) {
#pragma unroll
                for (int nf = 0; nf < 8; nf++) {
                    ins1(acc[nf][0], cbase + nf * 8,     v1a, i1a);
                    ins1(acc[nf][1], cbase + nf * 8 + 1, v1a, i1a);
                }
            }
            if (mB >= v1b) {
#pragma unroll
                for (int nf = 0; nf < 8; nf++) {
                    ins1(acc[nf][2], cbase + nf * 8,     v1b, i1b);
                    ins1(acc[nf][3], cbase + nf * 8 + 1, v1b, i1b);
                }
            }

            // ---- column fold, top-1 (only k>=2; no j==i there) ----
            if (k >= 2) {
#pragma unroll
                for (int nf = 0; nf < 8; nf++) {
#pragma unroll
                    for (int p = 0; p < 2; p++) {
                        float cv = acc[nf][p]; int ci = ra;
                        float cB = acc[nf][2 + p];
                        if (cB > cv) { cv = cB; ci = rb; }   // tie keeps ra (<rb)
#pragma unroll
                        for (int off = 4; off <= 16; off <<= 1) {
                            float ov = __shfl_xor_sync(0xffffffffu, cv, off);
                            int   oi = __shfl_xor_sync(0xffffffffu, ci, off);
                            if (ov > cv || (ov == cv && oi < ci)) { cv = ov; ci = oi; }
                        }
                        if (l < 4) {
                            int col = nf * 8 + l * 2 + p;
                            scv[w * 64 + col] = cv;
                            sci[w * 64 + col] = ci;
                        }
                    }
                }
                __syncthreads();
                if (t < 64) {
                    float m1 = -INFINITY; int x1 = 0x7fffffff;
#pragma unroll
                    for (int w8 = 0; w8 < 8; w8++)
                        ins1(scv[w8 * 64 + t], sci[w8 * 64 + t], m1, x1);
                    size_t base = (((size_t)b * NT64 + tj64) * NT128 + ti) * 64 + t;
                    g_cv[base] = m1;
                    g_ci[base] = x1;
                }
            }
        }

        // ---- write row-fold candidates for slot s ----
#pragma unroll
        for (int off = 1; off <= 2; off <<= 1) {
            float ov = __shfl_xor_sync(0xffffffffu, v1a, off);
            int   oi = __shfl_xor_sync(0xffffffffu, i1a, off);
            ins1(ov, oi, v1a, i1a);
            ov = __shfl_xor_sync(0xffffffffu, v1b, off);
            oi = __shfl_xor_sync(0xffffffffu, i1b, off);
            ins1(ov, oi, v1b, i1b);
        }
        if ((l & 3) == 0) {
            const size_t pa = (size_t)s * NPIX + b * NB + ra;
            const size_t pb = (size_t)s * NPIX + b * NB + rb;
            g_rv[pa] = v1a; g_ri[pa] = i1a;
            g_rv[pb] = v1b; g_ri[pb] = i1b;
        }
    }
}

// ---------------------------------------------------------------------------
// Merge row-fold (4 s-slots) + column-fold candidates -> g_nn per row.
// ---------------------------------------------------------------------------
__global__ void merge_kernel() {
    const int row = blockIdx.x * 256 + threadIdx.x;
    if (row >= NPIX) return;
    const int b = row / NB, jr = row % NB;
    const int tj64 = jr >> 6, rloc = jr & 63;
    float v1 = -INFINITY;
    int   i1 = 0x7fffffff;
#pragma unroll
    for (int s4 = 0; s4 < 4; s4++) {
        size_t p = (size_t)s4 * NPIX + row;
        ins1(g_rv[p], g_ri[p], v1, i1);
    }
    const int nti = (tj64 >= 2) ? (((tj64 - 2) >> 1) + 1) : 0;
    const size_t cb2 = (((size_t)b * NT64 + tj64) * NT128) * 64 + rloc;
    for (int ti = 0; ti < nti; ti++) {
        size_t p = cb2 + (size_t)ti * 64;
        ins1(g_cv[p], g_ci[p], v1, i1);
    }
    g_nn[row] = i1;
}

// ---------------------------------------------------------------------------
// Distance + mask: exact recomputation from fp32 rf (matches reference math).
// ---------------------------------------------------------------------------
__global__ void dist_kernel(float* __restrict__ out) {
    const int gw   = (int)((blockIdx.x * blockDim.x + threadIdx.x) >> 5);
    const int lane = threadIdx.x & 31;
    if (gw >= NPIX) return;
    const int b  = gw / NB;
    const int nn = g_nn[gw];
    const float* a = g_rf + (size_t)gw * C2;
    const float* c = g_rf + (size_t)(b * NB + nn) * C2;
    float4 av = *(const float4*)&a[lane * 4];
    float4 cv = *(const float4*)&c[lane * 4];
    float dx = av.x - cv.x, dy = av.y - cv.y, dz = av.z - cv.z, dw = av.w - cv.w;
    float s = dx * dx + dy * dy + dz * dz + dw * dw;
#pragma unroll
    for (int off = 16; off; off >>= 1) s += __shfl_xor_sync(0xffffffffu, s, off);
    if (lane == 0) {
        float d = sqrtf(s);
        out[NPIX + gw] = d;
        out[gw] = (d > MASK_THR) ? 1.0f : 0.0f;
    }
}

// ---------------------------------------------------------------------------
extern "C" void kernel_launch(void* const* d_in, const int* in_sizes, int n_in,
                              void* d_out, int out_size) {
    const float* features = (const float*)d_in[0];
    const float* W1 = (const float*)d_in[1];
    const float* b1 = (const float*)d_in[2];
    const float* W2 = (const float*)d_in[3];
    const float* b2 = (const float*)d_in[4];
    float* out = (float*)d_out;

    cudaFuncSetAttribute(sim_mma_kernel,
                         cudaFuncAttributeMaxDynamicSharedMemorySize, SIM_SMEM);
    cudaFuncSetAttribute(gemm1_mma_kernel,
                         cudaFuncAttributeMaxDynamicSharedMemorySize, MLP_SMEM);
    cudaFuncSetAttribute(gemm2_mma_kernel,
                         cudaFuncAttributeMaxDynamicSharedMemorySize, MLP_SMEM);

    splitw_kernel<<<(C1 * CIN + C2 * C1 + 255) / 256, 256>>>(W1, W2);
    transpose_split_kernel<<<dim3(NB / 32, CIN / 32, BATCH), dim3(32, 8)>>>(features);
    gemm1_mma_kernel<<<dim3(NPIX / 128, C1 / 64), 256, MLP_SMEM>>>(b1);
    gemm2_mma_kernel<<<dim3(NPIX / 128, C2 / 64), 256, MLP_SMEM>>>(b2);
    normalize_kernel<<<NPIX, 128>>>();
    sim_mma_kernel<<<dim3(36, 4, BATCH), 256, SIM_SMEM>>>();
    merge_kernel<<<NPIX / 256, 256>>>();
    dist_kernel<<<(NPIX * 32 + 255) / 256, 256>>>(out);
}

// round 16
// speedup vs baseline: 1.0034x; 1.0034x over previous
#include <cuda_runtime.h>
#include <cuda_fp16.h>
#include <math.h>
#include <stdint.h>

// Problem constants
#define BATCH 2
#define NB    9216          // H*W per batch (96*96)
#define NPIX  (BATCH * NB)  // 18432
#define CIN   384
#define C1    256
#define C2    128
#define MASK_THR 0.2f
#define NT64  144           // 64-row j-tiles per batch
#define NT128 72            // 128-row i-tiles per batch

// Scratch (device globals: no allocations allowed)
__device__ __align__(256) __half g_xth[(size_t)NPIX * CIN]; // X^T hi [bp][c]
__device__ __align__(256) __half g_xtl[(size_t)NPIX * CIN]; // X^T lo
__device__ __align__(256) __half g_w1h[(size_t)C1 * CIN];
__device__ __align__(256) __half g_w1l[(size_t)C1 * CIN];
__device__ __align__(256) __half g_w2h[(size_t)C2 * C1];
__device__ __align__(256) __half g_w2l[(size_t)C2 * C1];
__device__ __align__(256) __half g_h1h[(size_t)NPIX * C1];  // relu(h1) hi
__device__ __align__(256) __half g_h1l[(size_t)NPIX * C1];  // relu(h1) lo
__device__ float  g_feat[(size_t)NPIX * C2];   // [n][c]
__device__ float  g_rf[(size_t)NPIX * C2];     // [n][c] normalized fp32
__device__ __align__(256) __half g_hih[(size_t)NPIX * C2]; // rf fp16 hi
__device__ __align__(256) __half g_loh[(size_t)NPIX * C2]; // rf fp16 residual
// row-fold top-1 candidates: [s-slot 0..3][row]
__device__ float  g_rv[(size_t)4 * NPIX];
__device__ int    g_ri[(size_t)4 * NPIX];
// column-fold top-1 candidates: [batch][tj64][ti][64 rows]
__device__ float  g_cv[(size_t)BATCH * NT64 * NT128 * 64];
__device__ int    g_ci[(size_t)BATCH * NT64 * NT128 * 64];
__device__ int    g_nn[NPIX];

// ---------------------------------------------------------------------------
// PTX helpers (baseline ISA only — compute_103 safe)
// ---------------------------------------------------------------------------
__device__ __forceinline__ uint32_t smem_u32(const void* p) {
    return (uint32_t)__cvta_generic_to_shared(p);
}
#define CP16(dst, src) \
    asm volatile("cp.async.cg.shared.global [%0], [%1], 16;" :: "r"(dst), "l"(src))
#define CPCOMMIT() asm volatile("cp.async.commit_group;")
#define CPWAIT0()  asm volatile("cp.async.wait_group 0;" ::: "memory")

#define LDSM4(r0, r1, r2, r3, addr) \
    asm volatile("ldmatrix.sync.aligned.m8n8.x4.shared.b16 {%0,%1,%2,%3}, [%4];" \
        : "=r"(r0), "=r"(r1), "=r"(r2), "=r"(r3) : "r"(addr))

#define MMA16816(c, a, b) \
    asm volatile("mma.sync.aligned.m16n8k16.row.col.f32.f16.f16.f32 " \
        "{%0,%1,%2,%3}, {%4,%5,%6,%7}, {%8,%9}, {%0,%1,%2,%3};" \
        : "+f"((c)[0]), "+f"((c)[1]), "+f"((c)[2]), "+f"((c)[3]) \
        : "r"((a)[0]), "r"((a)[1]), "r"((a)[2]), "r"((a)[3]), \
          "r"((b)[0]), "r"((b)[1]))

// swizzle for 256B rows (sim kernel), 16B chunk c in 0..15
__device__ __forceinline__ uint32_t sw_off(int r, int c) {
    return (uint32_t)(r * 256 + ((c ^ (r & 7)) << 4));
}
// swizzle for 128B rows (MLP gemms), 16B chunk c in 0..7
__device__ __forceinline__ uint32_t sw128(int r, int c) {
    return (uint32_t)(r * 128 + ((c ^ (r & 7)) << 4));
}

// Top-1 insert with jax top_k tie-breaking (equal value -> lower index).
__device__ __forceinline__ void ins1(float v, int j, float& v1, int& i1) {
    if (v > v1 || (v == v1 && j < i1)) { v1 = v; i1 = j; }
}

// ---------------------------------------------------------------------------
// Prep: split W1/W2 into fp16 hi/lo
// ---------------------------------------------------------------------------
__global__ void splitw_kernel(const float* __restrict__ W1,
                              const float* __restrict__ W2) {
    int i = blockIdx.x * 256 + threadIdx.x;
    if (i < C1 * CIN) {
        float v = W1[i];
        __half h = __float2half_rn(v);
        g_w1h[i] = h;
        g_w1l[i] = __float2half_rn(v - __half2float(h));
    } else {
        int j = i - C1 * CIN;
        if (j < C2 * C1) {
            float v = W2[j];
            __half h = __float2half_rn(v);
            g_w2h[j] = h;
            g_w2l[j] = __float2half_rn(v - __half2float(h));
        }
    }
}

// ---------------------------------------------------------------------------
// Prep: transpose X [b][c][hw] -> Xt [b][hw][c], split fp16 hi/lo
// ---------------------------------------------------------------------------
__global__ void transpose_split_kernel(const float* __restrict__ X) {
    __shared__ float s[32][33];
    const int b = blockIdx.z;
    const int hw0 = blockIdx.x * 32;
    const int c0 = blockIdx.y * 32;
    const int tx = threadIdx.x, ty = threadIdx.y;
    const float* Xb = X + ((size_t)b * CIN + c0) * NB + hw0;
#pragma unroll
    for (int i = 0; i < 4; i++) {
        int cl = ty + 8 * i;
        s[cl][tx] = Xb[(size_t)cl * NB + tx];
    }
    __syncthreads();
#pragma unroll
    for (int i = 0; i < 4; i++) {
        int hwl = ty + 8 * i;
        float v = s[tx][hwl];
        __half h = __float2half_rn(v);
        size_t o = ((size_t)b * NB + hw0 + hwl) * CIN + c0 + tx;
        g_xth[o] = h;
        g_xtl[o] = __float2half_rn(v - __half2float(h));
    }
}

// ---------------------------------------------------------------------------
// Tensor-core MLP GEMM machinery (round-12, unchanged)
// ---------------------------------------------------------------------------
#define MLP_SMEM 98304

__device__ __forceinline__ void mlp_stage(uint32_t sb, int buf,
                                          const __half* __restrict__ Ah,
                                          const __half* __restrict__ Al,
                                          const __half* __restrict__ Bh,
                                          const __half* __restrict__ Bl,
                                          int m0, int n0, int kc0, int K, int t) {
    const uint32_t sA = sb + (uint32_t)buf * 32768u;
    const uint32_t sB = sb + 65536u + (uint32_t)buf * 16384u;
#pragma unroll
    for (int e = 0; e < 4; e++) {
        int id = e * 256 + t;
        int r = id >> 3, c = id & 7;
        uint32_t o = sw128(r, c);
        const size_t off = (size_t)(m0 + r) * K + kc0 + c * 8;
        CP16(sA + o,          Ah + off);
        CP16(sA + 16384u + o, Al + off);
    }
#pragma unroll
    for (int e = 0; e < 2; e++) {
        int id = e * 256 + t;
        int r = id >> 3, c = id & 7;
        uint32_t o = sw128(r, c);
        const size_t off = (size_t)(n0 + r) * K + kc0 + c * 8;
        CP16(sB + o,         Bh + off);
        CP16(sB + 8192u + o, Bl + off);
    }
}

#define MLP_COMPUTE_CHUNK(aB, bB)                                              \
    _Pragma("unroll")                                                          \
    for (int ks = 0; ks < 4; ks++) {                                           \
        const int ck = ks * 2;                                                 \
        uint32_t ah[4], al[4];                                                 \
        LDSM4(ah[0], ah[1], ah[2], ah[3], (aB) + sw128(ar, ck + cb));          \
        LDSM4(al[0], al[1], al[2], al[3], (aB) + 16384u + sw128(ar, ck + cb)); \
        uint32_t bf[16];                                                       \
        _Pragma("unroll")                                                      \
        for (int nb = 0; nb < 4; nb++) {                                       \
            uint32_t ad = (bB) + sw128(nb * 16 + brn, ck + bcb);               \
            LDSM4(bf[4*nb], bf[4*nb+1], bf[4*nb+2], bf[4*nb+3], ad);           \
        }                                                                      \
        _Pragma("unroll")                                                      \
        for (int nf = 0; nf < 8; nf++) MMA16816(acc[nf], ah, bf + 2 * nf);     \
        _Pragma("unroll")                                                      \
        for (int nf = 0; nf < 8; nf++) MMA16816(acc[nf], al, bf + 2 * nf);     \
        _Pragma("unroll")                                                      \
        for (int nb = 0; nb < 4; nb++) {                                       \
            uint32_t ad = (bB) + 8192u + sw128(nb * 16 + brn, ck + bcb);       \
            LDSM4(bf[4*nb], bf[4*nb+1], bf[4*nb+2], bf[4*nb+3], ad);           \
        }                                                                      \
        _Pragma("unroll")                                                      \
        for (int nf = 0; nf < 8; nf++) MMA16816(acc[nf], ah, bf + 2 * nf);     \
    }

__global__ void __launch_bounds__(256, 2) gemm1_mma_kernel(const float* __restrict__ b1v) {
    extern __shared__ __align__(1024) char sm[];
    const int t = threadIdx.x, w = t >> 5, l = t & 31;
    const int m0 = blockIdx.x * 128, n0 = blockIdx.y * 64;
    const uint32_t sb = smem_u32(sm);
    const int sub = l >> 3;
    const int ar  = w * 16 + ((sub & 1) << 3) + (l & 7);
    const int cb  = sub >> 1;
    const int brn = ((sub >> 1) << 3) + (l & 7);
    const int bcb = sub & 1;

    mlp_stage(sb, 0, g_xth, g_xtl, g_w1h, g_w1l, m0, n0, 0, CIN, t);
    CPCOMMIT();

    float acc[8][4];
#pragma unroll
    for (int nf = 0; nf < 8; nf++)
#pragma unroll
        for (int q = 0; q < 4; q++) acc[nf][q] = 0.f;

    const int NCH = CIN / 64;
    for (int kc = 0; kc < NCH; kc++) {
        CPWAIT0();
        __syncthreads();
        if (kc + 1 < NCH) {
            mlp_stage(sb, (kc + 1) & 1, g_xth, g_xtl, g_w1h, g_w1l,
                      m0, n0, (kc + 1) * 64, CIN, t);
            CPCOMMIT();
        }
        const uint32_t aB = sb + (uint32_t)(kc & 1) * 32768u;
        const uint32_t bB = sb + 65536u + (uint32_t)(kc & 1) * 16384u;
        MLP_COMPUTE_CHUNK(aB, bB)
        __syncthreads();
    }

    const int rowa = m0 + w * 16 + (l >> 2);
#pragma unroll
    for (int nf = 0; nf < 8; nf++) {
        int col = n0 + nf * 8 + (l & 3) * 2;
        float b0 = b1v[col], b1 = b1v[col + 1];
        float v0 = fmaxf(acc[nf][0] + b0, 0.f);
        float v1 = fmaxf(acc[nf][1] + b1, 0.f);
        float v2 = fmaxf(acc[nf][2] + b0, 0.f);
        float v3 = fmaxf(acc[nf][3] + b1, 0.f);
        __half h0 = __float2half_rn(v0), h1 = __float2half_rn(v1);
        __half h2 = __float2half_rn(v2), h3 = __float2half_rn(v3);
        *(__half2*)&g_h1h[(size_t)rowa * C1 + col] = __halves2half2(h0, h1);
        *(__half2*)&g_h1l[(size_t)rowa * C1 + col] = __halves2half2(
            __float2half_rn(v0 - __half2float(h0)),
            __float2half_rn(v1 - __half2float(h1)));
        *(__half2*)&g_h1h[(size_t)(rowa + 8) * C1 + col] = __halves2half2(h2, h3);
        *(__half2*)&g_h1l[(size_t)(rowa + 8) * C1 + col] = __halves2half2(
            __float2half_rn(v2 - __half2float(h2)),
            __float2half_rn(v3 - __half2float(h3)));
    }
}

__global__ void __launch_bounds__(256, 2) gemm2_mma_kernel(const float* __restrict__ b2v) {
    extern __shared__ __align__(1024) char sm[];
    const int t = threadIdx.x, w = t >> 5, l = t & 31;
    const int m0 = blockIdx.x * 128, n0 = blockIdx.y * 64;
    const uint32_t sb = smem_u32(sm);
    const int sub = l >> 3;
    const int ar  = w * 16 + ((sub & 1) << 3) + (l & 7);
    const int cb  = sub >> 1;
    const int brn = ((sub >> 1) << 3) + (l & 7);
    const int bcb = sub & 1;

    mlp_stage(sb, 0, g_h1h, g_h1l, g_w2h, g_w2l, m0, n0, 0, C1, t);
    CPCOMMIT();

    float acc[8][4];
#pragma unroll
    for (int nf = 0; nf < 8; nf++)
#pragma unroll
        for (int q = 0; q < 4; q++) acc[nf][q] = 0.f;

    const int NCH = C1 / 64;
    for (int kc = 0; kc < NCH; kc++) {
        CPWAIT0();
        __syncthreads();
        if (kc + 1 < NCH) {
            mlp_stage(sb, (kc + 1) & 1, g_h1h, g_h1l, g_w2h, g_w2l,
                      m0, n0, (kc + 1) * 64, C1, t);
            CPCOMMIT();
        }
        const uint32_t aB = sb + (uint32_t)(kc & 1) * 32768u;
        const uint32_t bB = sb + 65536u + (uint32_t)(kc & 1) * 16384u;
        MLP_COMPUTE_CHUNK(aB, bB)
        __syncthreads();
    }

    const int rowa = m0 + w * 16 + (l >> 2);
#pragma unroll
    for (int nf = 0; nf < 8; nf++) {
        int col = n0 + nf * 8 + (l & 3) * 2;
        float b0 = b2v[col], b1 = b2v[col + 1];
        float2 ra = make_float2(acc[nf][0] + b0, acc[nf][1] + b1);
        float2 rb = make_float2(acc[nf][2] + b0, acc[nf][3] + b1);
        *(float2*)&g_feat[(size_t)rowa * C2 + col] = ra;
        *(float2*)&g_feat[(size_t)(rowa + 8) * C2 + col] = rb;
    }
}

// ---------------------------------------------------------------------------
// Normalize: rf = feat / max(||feat||, 1e-12); fp32 rf + fp16 hi/lo split.
// ---------------------------------------------------------------------------
__global__ void normalize_kernel() {
    const int n = blockIdx.x;
    const int c = threadIdx.x;
    float v = g_feat[(size_t)n * C2 + c];
    float s = v * v;
#pragma unroll
    for (int off = 16; off; off >>= 1) s += __shfl_xor_sync(0xffffffffu, s, off);
    __shared__ float ws[4];
    if ((c & 31) == 0) ws[c >> 5] = s;
    __syncthreads();
    float tot = ws[0] + ws[1] + ws[2] + ws[3];
    float norm = sqrtf(tot);
    float nf = v / fmaxf(norm, 1e-12f);
    g_rf[(size_t)n * C2 + c] = nf;
    __half hi = __float2half_rn(nf);
    g_hih[(size_t)n * C2 + c] = hi;
    g_loh[(size_t)n * C2 + c] = __float2half_rn(nf - __half2float(hi));
}

// ---------------------------------------------------------------------------
// SYMMETRIC tensor-core similarity, TOP-1-excluding-self version.
// Since sim(i,i)=1 is always row top-1 (unit vectors), the reference's
// top2_idx[:,:,1] == argmax_{j != i} sim(i,j)  (ties -> lower index).
// Each unordered tile pair computed once; folded into row top-1 (i-rows)
// and column top-1 (j-rows).  Diagonal (j==i) masked to -inf in k<2 tiles.
// Partition (validated in R13): row-cover k=tj64-2*ti in [0,nt);
// column-cover only k>=2 (no double count, no self in column side).
// Grid: (36 pair-ids, 4 s, 2 batches) = 288 CTAs -> 2 CTAs/SM.
// ---------------------------------------------------------------------------
#define ALO_BYTES 32768
#define BUFB  32768
#define SIM_SMEM (ALO_BYTES + 2 * BUFB + 4096)   // 100KB

__global__ void __launch_bounds__(256, 2) sim_mma_kernel() {
    extern __shared__ __align__(1024) char sm[];
    const int t = threadIdx.x;
    const int w = t >> 5, l = t & 31;
    const int pid = blockIdx.x;      // 0..35
    const int s   = blockIdx.y;      // 0..3
    const int b   = blockIdx.z;
    const __half* Hsrc = g_hih + (size_t)b * NB * C2;
    const __half* Lsrc = g_loh + (size_t)b * NB * C2;
    const uint32_t sbA = smem_u32(sm);
    const uint32_t bb0 = sbA + ALO_BYTES;
    float* scv = (float*)(sm + ALO_BYTES + 2 * BUFB);
    int*   sci = (int*)(sm + ALO_BYTES + 2 * BUFB + 2048);

    const int sub = l >> 3;
    const int arl = ((sub & 1) << 3) + (l & 7);
    const int cb  = sub >> 1;
    const int ar  = w * 16 + arl;
    const int brn = ((sub >> 1) << 3) + (l & 7);
    const int bcb = sub & 1;

    for (int phase = 0; phase < 2; phase++) {
        const int ti = phase ? (71 - pid) : pid;
        const int i0 = ti * 128;
        const int nt = NT64 - 2 * ti;
        const int count = (nt > s) ? ((nt - s + 3) >> 2) : 0;
        const int ra = i0 + w * 16 + (l >> 2);   // batch-local row A
        const int rb = ra + 8;                    // batch-local row B

        float v1a = -INFINITY, v1b = -INFINITY;
        int   i1a = 0x7fffffff, i1b = 0x7fffffff;

        uint32_t a_hi[8][4];

        if (count > 0) {
            __syncthreads();   // prior phase fully done with B region / colbuf
#pragma unroll
            for (int e = 0; e < 8; e++) {
                int id = e * 256 + t;
                int r = id >> 4, c = id & 15;
                uint32_t o = sw_off(r, c);
                CP16(sbA + o, (const char*)(Lsrc + (size_t)(i0 + r) * C2) + c * 16);
                CP16(bb0 + o, (const char*)(Hsrc + (size_t)(i0 + r) * C2) + c * 16);
            }
            CPCOMMIT(); CPWAIT0();
            __syncthreads();
#pragma unroll
            for (int ks = 0; ks < 8; ks++) {
                uint32_t ad = bb0 + sw_off(ar, ks * 2 + cb);
                LDSM4(a_hi[ks][0], a_hi[ks][1], a_hi[ks][2], a_hi[ks][3], ad);
            }
            __syncthreads();
            {
                const int j0 = (2 * ti + s) * 64;
#pragma unroll
                for (int e = 0; e < 4; e++) {
                    int id = e * 256 + t;
                    int r = id >> 4, c = id & 15;
                    uint32_t o = sw_off(r, c);
                    CP16(bb0 + o,         (const char*)(Hsrc + (size_t)(j0 + r) * C2) + c * 16);
                    CP16(bb0 + 16384 + o, (const char*)(Lsrc + (size_t)(j0 + r) * C2) + c * 16);
                }
                CPCOMMIT();
            }
        }

        for (int m = 0; m < count; m++) {
            const int k = s + 4 * m;
            const int tj64 = 2 * ti + k;
            CPWAIT0();
            __syncthreads();

            if (m + 1 < count) {
                const int j0n = (tj64 + 4) * 64;
                const uint32_t bo = bb0 + (uint32_t)((m + 1) & 1) * BUFB;
#pragma unroll
                for (int e = 0; e < 4; e++) {
                    int id = e * 256 + t;
                    int r = id >> 4, c = id & 15;
                    uint32_t o = bo + sw_off(r, c);
                    CP16(o,         (const char*)(Hsrc + (size_t)(j0n + r) * C2) + c * 16);
                    CP16(o + 16384, (const char*)(Lsrc + (size_t)(j0n + r) * C2) + c * 16);
                }
                CPCOMMIT();
            }

            const uint32_t bo = bb0 + (uint32_t)(m & 1) * BUFB;
            float acc[8][4];
#pragma unroll
            for (int nf = 0; nf < 8; nf++)
#pragma unroll
                for (int q = 0; q < 4; q++) acc[nf][q] = 0.f;

#pragma unroll
            for (int ks = 0; ks < 8; ks++) {
                const int ck = ks * 2;
                uint32_t al[4];
                LDSM4(al[0], al[1], al[2], al[3], sbA + sw_off(ar, ck + cb));
                uint32_t bf[16];
#pragma unroll
                for (int nb = 0; nb < 4; nb++) {
                    uint32_t ad = bo + sw_off(nb * 16 + brn, ck + bcb);
                    LDSM4(bf[4 * nb], bf[4 * nb + 1], bf[4 * nb + 2], bf[4 * nb + 3], ad);
                }
#pragma unroll
                for (int nf = 0; nf < 8; nf++) MMA16816(acc[nf], a_hi[ks], bf + 2 * nf);
#pragma unroll
                for (int nf = 0; nf < 8; nf++) MMA16816(acc[nf], al, bf + 2 * nf);
#pragma unroll
                for (int nb = 0; nb < 4; nb++) {
                    uint32_t ad = bo + 16384 + sw_off(nb * 16 + brn, ck + bcb);
                    LDSM4(bf[4 * nb], bf[4 * nb + 1], bf[4 * nb + 2], bf[4 * nb + 3], ad);
                }
#pragma unroll
                for (int nf = 0; nf < 8; nf++) MMA16816(acc[nf], a_hi[ks], bf + 2 * nf);
            }

            const int cbase = tj64 * 64 + (l & 3) * 2;

            // ---- diagonal mask (only k<2 tiles can contain j==i) ----
            if (k < 2) {
#pragma unroll
                for (int nf = 0; nf < 8; nf++) {
                    int c0 = cbase + nf * 8, c1 = c0 + 1;
                    if (c0 == ra) acc[nf][0] = -INFINITY;
                    if (c1 == ra) acc[nf][1] = -INFINITY;
                    if (c0 == rb) acc[nf][2] = -INFINITY;
                    if (c1 == rb) acc[nf][3] = -INFINITY;
                }
            }

            // ---- row fold, top-1, guarded ----
            float mA = fmaxf(acc[0][0], acc[0][1]);
            float mB = fmaxf(acc[0][2], acc[0][3]);
#pragma unroll
            for (int nf = 1; nf < 8; nf++) {
                mA = fmaxf(mA, fmaxf(acc[nf][0], acc[nf][1]));
                mB = fmaxf(mB, fmaxf(acc[nf][2], acc[nf][3]));
            }
            if (mA >= v1a) {
#pragma unroll
                for (int nf = 0; nf < 8; nf++) {
                    ins1(acc[nf][0], cbase + nf * 8,     v1a, i1a);
                    ins1(acc[nf][1], cbase + nf * 8 + 1, v1a, i1a);
                }
            }
            if (mB >= v1b) {
#pragma unroll
                for (int nf = 0; nf < 8; nf++) {
                    ins1(acc[nf][2], cbase + nf * 8,     v1b, i1b);
                    ins1(acc[nf][3], cbase + nf * 8 + 1, v1b, i1b);
                }
            }

            // ---- column fold, top-1 (only k>=2; no j==i there) ----
            if (k >= 2) {
#pragma unroll
                for (int nf = 0; nf < 8; nf++) {
#pragma unroll
                    for (int p = 0; p < 2; p++) {
                        float cv = acc[nf][p]; int ci = ra;
                        float cB = acc[nf][2 + p];
                        if (cB > cv) { cv = cB; ci = rb; }   // tie keeps ra (<rb)
#pragma unroll
                        for (int off = 4; off <= 16; off <<= 1) {
                            float ov = __shfl_xor_sync(0xffffffffu, cv, off);
                            int   oi = __shfl_xor_sync(0xffffffffu, ci, off);
                            if (ov > cv || (ov == cv && oi < ci)) { cv = ov; ci = oi; }
                        }
                        if (l < 4) {
                            int col = nf * 8 + l * 2 + p;
                            scv[w * 64 + col] = cv;
                            sci[w * 64 + col] = ci;
                        }
                    }
                }
                __syncthreads();
                if (t < 64) {
                    float m1 = -INFINITY; int x1 = 0x7fffffff;
#pragma unroll
                    for (int w8 = 0; w8 < 8; w8++)
                        ins1(scv[w8 * 64 + t], sci[w8 * 64 + t], m1, x1);
                    size_t base = (((size_t)b * NT64 + tj64) * NT128 + ti) * 64 + t;
                    g_cv[base] = m1;
                    g_ci[base] = x1;
                }
            }
        }

        // ---- write row-fold candidates for slot s ----
#pragma unroll
        for (int off = 1; off <= 2; off <<= 1) {
            float ov = __shfl_xor_sync(0xffffffffu, v1a, off);
            int   oi = __shfl_xor_sync(0xffffffffu, i1a, off);
            ins1(ov, oi, v1a, i1a);
            ov = __shfl_xor_sync(0xffffffffu, v1b, off);
            oi = __shfl_xor_sync(0xffffffffu, i1b, off);
            ins1(ov, oi, v1b, i1b);
        }
        if ((l & 3) == 0) {
            const size_t pa = (size_t)s * NPIX + b * NB + ra;
            const size_t pb = (size_t)s * NPIX + b * NB + rb;
            g_rv[pa] = v1a; g_ri[pa] = i1a;
            g_rv[pb] = v1b; g_ri[pb] = i1b;
        }
    }
}

// ---------------------------------------------------------------------------
// Merge row-fold (4 s-slots) + column-fold candidates -> g_nn per row.
// ---------------------------------------------------------------------------
__global__ void merge_kernel() {
    const int row = blockIdx.x * 256 + threadIdx.x;
    if (row >= NPIX) return;
    const int b = row / NB, jr = row % NB;
    const int tj64 = jr >> 6, rloc = jr & 63;
    float v1 = -INFINITY;
    int   i1 = 0x7fffffff;
#pragma unroll
    for (int s4 = 0; s4 < 4; s4++) {
        size_t p = (size_t)s4 * NPIX + row;
        ins1(g_rv[p], g_ri[p], v1, i1);
    }
    const int nti = (tj64 >= 2) ? (((tj64 - 2) >> 1) + 1) : 0;
    const size_t cb2 = (((size_t)b * NT64 + tj64) * NT128) * 64 + rloc;
    for (int ti = 0; ti < nti; ti++) {
        size_t p = cb2 + (size_t)ti * 64;
        ins1(g_cv[p], g_ci[p], v1, i1);
    }
    g_nn[row] = i1;
}

// ---------------------------------------------------------------------------
// Distance + mask: exact recomputation from fp32 rf (matches reference math).
// ---------------------------------------------------------------------------
__global__ void dist_kernel(float* __restrict__ out) {
    const int gw   = (int)((blockIdx.x * blockDim.x + threadIdx.x) >> 5);
    const int lane = threadIdx.x & 31;
    if (gw >= NPIX) return;
    const int b  = gw / NB;
    const int nn = g_nn[gw];
    const float* a = g_rf + (size_t)gw * C2;
    const float* c = g_rf + (size_t)(b * NB + nn) * C2;
    float4 av = *(const float4*)&a[lane * 4];
    float4 cv = *(const float4*)&c[lane * 4];
    float dx = av.x - cv.x, dy = av.y - cv.y, dz = av.z - cv.z, dw = av.w - cv.w;
    float s = dx * dx + dy * dy + dz * dz + dw * dw;
#pragma unroll
    for (int off = 16; off; off >>= 1) s += __shfl_xor_sync(0xffffffffu, s, off);
    if (lane == 0) {
        float d = sqrtf(s);
        out[NPIX + gw] = d;
        out[gw] = (d > MASK_THR) ? 1.0f : 0.0f;
    }
}

// ---------------------------------------------------------------------------
extern "C" void kernel_launch(void* const* d_in, const int* in_sizes, int n_in,
                              void* d_out, int out_size) {
    const float* features = (const float*)d_in[0];
    const float* W1 = (const float*)d_in[1];
    const float* b1 = (const float*)d_in[2];
    const float* W2 = (const float*)d_in[3];
    const float* b2 = (const float*)d_in[4];
    float* out = (float*)d_out;

    cudaFuncSetAttribute(sim_mma_kernel,
                         cudaFuncAttributeMaxDynamicSharedMemorySize, SIM_SMEM);
    cudaFuncSetAttribute(gemm1_mma_kernel,
                         cudaFuncAttributeMaxDynamicSharedMemorySize, MLP_SMEM);
    cudaFuncSetAttribute(gemm2_mma_kernel,
                         cudaFuncAttributeMaxDynamicSharedMemorySize, MLP_SMEM);

    splitw_kernel<<<(C1 * CIN + C2 * C1 + 255) / 256, 256>>>(W1, W2);
    transpose_split_kernel<<<dim3(NB / 32, CIN / 32, BATCH), dim3(32, 8)>>>(features);
    gemm1_mma_kernel<<<dim3(NPIX / 128, C1 / 64), 256, MLP_SMEM>>>(b1);
    gemm2_mma_kernel<<<dim3(NPIX / 128, C2 / 64), 256, MLP_SMEM>>>(b2);
    normalize_kernel<<<NPIX, 128>>>();
    sim_mma_kernel<<<dim3(36, 4, BATCH), 256, SIM_SMEM>>>();
    merge_kernel<<<NPIX / 256, 256>>>();
    dist_kernel<<<(NPIX * 32 + 255) / 256, 256>>>(out);
}